// round 16
// baseline (speedup 1.0000x reference)
#include <cuda_runtime.h>
#include <cstdint>
#include <cstddef>

#define SEQ   128
#define BATCH 256
#define OBS   64
#define HID   1024
#define GATES 4096
#define NBLK  128
#define NTHR  512
#define BH    (BATCH * HID)

// ---- fp32 scratch ----
__device__ float g_h[2 * BH];
__device__ float g_c[2 * BH];
__device__ float g_hs[(size_t)SEQ * BH];
__device__ float g_a3[(size_t)SEQ * BATCH * 64];
__device__ float g_bias0[GATES];        // gate-interleaved bih0+bhh0
__device__ float g_bias1[GATES];

// ---- packed B (weights). LSTM mats are gate-interleaved: ng = ublock*4+gate
__device__ uint4 pk_ih0[(size_t)2048  * 32];
__device__ uint4 pk_hh0[(size_t)32768 * 32];
__device__ uint4 pk_ih1[(size_t)32768 * 32];
__device__ uint4 pk_hh1[(size_t)32768 * 32];
__device__ uint4 pk_W1 [(size_t)4096  * 32];
__device__ uint4 pk_W2 [(size_t)512   * 32];
__device__ uint4 pk_W3 [(size_t)64    * 32];

// ---- packed A (activations) ----
__device__ uint4 g_xpack[(size_t)8192 * 64];
__device__ uint4 g_h0m[2][(size_t)1024 * 64];   // double-buffered (t parity)
__device__ uint4 g_h0u[(size_t)1024 * 64];
__device__ uint4 g_h1m[2][(size_t)1024 * 64];
__device__ uint4 g_hsp[(size_t)131072 * 64];
__device__ uint4 g_a1p[(size_t)65536 * 64];
__device__ uint4 g_a2p[(size_t)16384 * 64];

// ---- grid barrier ----
__device__ unsigned g_arr = 0;
__device__ volatile unsigned g_rel = 0;

__device__ __forceinline__ void grid_sync() {
    __syncthreads();
    if (threadIdx.x == 0) {
        __threadfence();
        unsigned v = atomicAdd(&g_arr, 1u);
        unsigned target = v / NBLK + 1u;
        if ((v % NBLK) == NBLK - 1u) g_rel = target;
        else while (g_rel < target) { }
        __threadfence();
    }
    __syncthreads();
}

__device__ __forceinline__ float sigm(float x) { return 1.0f / (1.0f + expf(-x)); }

__device__ __forceinline__ uint32_t smem_u32_of(const void* p) {
    uint32_t a;
    asm("{ .reg .u64 t; cvta.to.shared.u64 t, %1; cvt.u32.u64 %0, t; }" : "=r"(a) : "l"(p));
    return a;
}
__device__ __forceinline__ uint4 lds128(uint32_t a) {
    uint4 v;
    asm volatile("ld.shared.v4.u32 {%0,%1,%2,%3}, [%4];"
                 : "=r"(v.x), "=r"(v.y), "=r"(v.z), "=r"(v.w) : "r"(a));
    return v;
}
__device__ __forceinline__ void cpasync16(uint32_t dst, const void* src, uint32_t sz) {
    asm volatile("cp.async.cg.shared.global [%0], [%1], 16, %2;"
                 :: "r"(dst), "l"(src), "r"(sz) : "memory");
}
#define CP_COMMIT() asm volatile("cp.async.commit_group;" ::: "memory")
#define CP_WAIT4()  asm volatile("cp.async.wait_group 4;" ::: "memory")

__device__ __forceinline__ uint32_t bfsplit(float x0, float x1, uint32_t& lo) {
    uint32_t h;
    asm("cvt.rn.bf16x2.f32 %0, %1, %2;" : "=r"(h) : "f"(x1), "f"(x0));
    float h0 = __uint_as_float(h << 16);
    float h1 = __uint_as_float(h & 0xFFFF0000u);
    float l0 = x0 - h0, l1 = x1 - h1;
    asm("cvt.rn.bf16x2.f32 %0, %1, %2;" : "=r"(lo) : "f"(l1), "f"(l0));
    return h;
}
__device__ __forceinline__ void mma16(float d[4], const uint32_t a[4],
                                      uint32_t b0, uint32_t b1) {
    asm("mma.sync.aligned.m16n8k16.row.col.f32.bf16.bf16.f32 "
        "{%0,%1,%2,%3}, {%4,%5,%6,%7}, {%8,%9}, {%0,%1,%2,%3};"
        : "+f"(d[0]), "+f"(d[1]), "+f"(d[2]), "+f"(d[3])
        : "r"(a[0]), "r"(a[1]), "r"(a[2]), "r"(a[3]), "r"(b0), "r"(b1));
}

// ---- prepack: weights (LSTM gate-interleaved), x frags, combined biases ----
#define NWFRAG 105024
#define NFRAG  (NWFRAG + 8192)
__global__ __launch_bounds__(NTHR) void prepack_kernel(
    const float* __restrict__ Wih0, const float* __restrict__ Whh0,
    const float* __restrict__ Wih1, const float* __restrict__ Whh1,
    const float* __restrict__ W1,  const float* __restrict__ W2,
    const float* __restrict__ W3,  const float* __restrict__ x,
    const float* __restrict__ bih0, const float* __restrict__ bhh0,
    const float* __restrict__ bih1, const float* __restrict__ bhh1)
{
    const int total = NFRAG * 32 + 2 * GATES;
    for (int t = blockIdx.x * blockDim.x + threadIdx.x; t < total;
         t += gridDim.x * blockDim.x) {
        if (t < NWFRAG * 32) {
            const int f = t >> 5, lane = t & 31;
            const int g = lane >> 2, tig = lane & 3;
            const float* W; uint4* pk; int ns, K, fl; bool lstm;
            if      (f < 2048)   { W=Wih0; pk=pk_ih0; ns=4;  K=64;   fl=f;        lstm=true; }
            else if (f < 34816)  { W=Whh0; pk=pk_hh0; ns=64; K=1024; fl=f-2048;   lstm=true; }
            else if (f < 67584)  { W=Wih1; pk=pk_ih1; ns=64; K=1024; fl=f-34816;  lstm=true; }
            else if (f < 100352) { W=Whh1; pk=pk_hh1; ns=64; K=1024; fl=f-67584;  lstm=true; }
            else if (f < 104448) { W=W1;   pk=pk_W1;  ns=64; K=1024; fl=f-100352; lstm=false; }
            else if (f < 104960) { W=W2;   pk=pk_W2;  ns=32; K=512;  fl=f-104448; lstm=false; }
            else                 { W=W3;   pk=pk_W3;  ns=8;  K=128;  fl=f-104960; lstm=false; }
            const int ng = fl / ns, s = fl - ng * ns;
            const int row = lstm ? ((ng & 3) * 1024 + (ng >> 2) * 8 + g)
                                 : (ng * 8 + g);
            const float* wp = W + (size_t)row * K + s * 16 + 2 * tig;
            uint32_t l01, l23;
            uint32_t h01 = bfsplit(wp[0], wp[1], l01);
            uint32_t h23 = bfsplit(wp[8], wp[9], l23);
            pk[(size_t)fl * 32 + lane] = make_uint4(h01, h23, l01, l23);
        } else if (t < NFRAG * 32) {
            const int f = t >> 5, lane = t & 31;
            const int g = lane >> 2, tig = lane & 3;
            const int fx = f - NWFRAG;
            const int ts = fx >> 6, mg = (fx >> 2) & 15, s = fx & 3;
            const int r0 = ts * 256 + mg * 16 + g, r1 = r0 + 8;
            const int c0 = s * 16 + 2 * tig;
            const float* p0 = x + (size_t)r0 * OBS + c0;
            const float* p1 = x + (size_t)r1 * OBS + c0;
            uint32_t l0, l1, l2, l3;
            uint32_t a0 = bfsplit(p0[0], p0[1], l0);
            uint32_t a1 = bfsplit(p1[0], p1[1], l1);
            uint32_t a2 = bfsplit(p0[8], p0[9], l2);
            uint32_t a3 = bfsplit(p1[8], p1[9], l3);
            uint4* d = g_xpack + (size_t)fx * 64 + lane * 2;
            d[0] = make_uint4(a0, a1, a2, a3);
            d[1] = make_uint4(l0, l1, l2, l3);
        } else {
            const int j = t - NFRAG * 32;
            const int layer = j >> 12, col = j & 4095;
            const int ng = col >> 3, gr = col & 7;
            const int row = (ng & 3) * 1024 + (ng >> 2) * 8 + gr;
            if (layer == 0) g_bias0[col] = bih0[row] + bhh0[row];
            else            g_bias1[col] = bih1[row] + bhh1[row];
        }
    }
}

// GEMM. 8-stage cp.async smem pipeline (A + B[nt0,1]) + 2-deep LDG reg
// pipeline (B[nt2,3]). CTA 64x128, 16 warps (4m x 4n), warp 16x32.
// epi: 0 = f32 C (+bias,+ELU), 1 = packed frag out (+bias,+ELU),
//      2 = fused LSTM cell (gate-interleaved B; bias = packed combined).
__device__ void gemm_mma(char* smdyn, int M, int N,
                         const uint4* __restrict__ Af0, int ns0,
                         const uint4* __restrict__ Af1, int ns1,
                         const uint4* __restrict__ PK0,
                         const uint4* __restrict__ PK1,
                         const float* __restrict__ bias,
                         float* __restrict__ C, int ldc, int act,
                         uint4* __restrict__ Cp, int nsCp,
                         int epi, int layer,
                         const int* __restrict__ done_t,
                         uint4* __restrict__ pk_u,
                         uint4* __restrict__ pk_m,
                         const int* __restrict__ done_next,
                         float* __restrict__ hs_out)
{
    const uint32_t smb = smem_u32_of(smdyn);
    const int tid = threadIdx.x, lane = tid & 31, wid = tid >> 5;
    const int warp_m = wid & 3, warp_n = wid >> 2;
    const int g = lane >> 2, tg = lane & 3;
    const int ns = ns0 + ns1;
    const int ntm = M / 64, ntn = (N + 127) / 128;

    const bool isA = tid < 256;
    uint32_t dstoff; int mgl = 0, eA = 0, ngl = 0, eB = 0;
    if (isA) {
        mgl = tid >> 6; eA = tid & 63;
        dstoff = (uint32_t)(mgl * 1024 + (eA & 1) * 512 + (eA >> 1) * 16);
    } else {
        const int j = tid - 256;
        const int fr = j >> 5; eB = j & 31;
        ngl = (fr >> 1) * 4 + (fr & 1);
        dstoff = (uint32_t)(4096 + fr * 512 + eB * 16);
    }

    for (int u = blockIdx.x; u < ntm * ntn; u += NBLK) {
        const int m0 = (u % ntm) * 64, n0 = (u / ntm) * 128;
        const int mg0 = m0 >> 4;
        const int ngb = (n0 >> 3) + warp_n * 4;

        const uint4* srcA0 = nullptr; const uint4* srcA1 = nullptr;
        const uint4* srcB0 = nullptr; const uint4* srcB1 = nullptr;
        uint32_t bsz = 16;
        if (isA) {
            const int mgA = mg0 + mgl;
            srcA0 = Af0 + (size_t)mgA * ns0 * 64 + eA;
            if (Af1) srcA1 = Af1 + (size_t)mgA * ns1 * 64 + eA;
        } else {
            const int ngT = (n0 >> 3) + ngl;
            const bool bv = ngT * 8 < N;
            bsz = bv ? 16u : 0u;
            srcB0 = PK0 + (bv ? (size_t)ngT * ns0 * 32 : 0) + eB;
            if (PK1) srcB1 = PK1 + (bv ? (size_t)ngT * ns1 * 32 : 0) + eB;
        }
        const int ng2 = ngb + 2, ng3 = ngb + 3;
        const bool v2 = ng2 * 8 < N, v3 = ng3 * 8 < N;
        const uint4* pB2_0 = PK0 + (v2 ? (size_t)ng2 * ns0 * 32 : 0) + lane;
        const uint4* pB3_0 = PK0 + (v3 ? (size_t)ng3 * ns0 * 32 : 0) + lane;
        const uint4* pB2_1 = PK1 ? PK1 + (v2 ? (size_t)ng2 * ns1 * 32 : 0) + lane : nullptr;
        const uint4* pB3_1 = PK1 ? PK1 + (v3 ? (size_t)ng3 * ns1 * 32 : 0) + lane : nullptr;

        float acc[4][4];
        #pragma unroll
        for (int i = 0; i < 4; i++)
            #pragma unroll
            for (int j2 = 0; j2 < 4; j2++) acc[i][j2] = 0.f;

        uint4 q2a = make_uint4(0,0,0,0), q3a = q2a, q2b = q2a, q3b = q2a;

        auto ldg2 = [&](int s, uint4& q2, uint4& q3) {
            if (s >= ns) return;
            if (s < ns0) {
                if (v2) q2 = pB2_0[(size_t)s * 32];
                if (v3) q3 = pB3_0[(size_t)s * 32];
            } else {
                if (v2) q2 = pB2_1[(size_t)(s - ns0) * 32];
                if (v3) q3 = pB3_1[(size_t)(s - ns0) * 32];
            }
        };
        auto issue = [&](int s) {
            if (s < ns) {
                const uint32_t d = smb + (uint32_t)(s & 7) * 8192u + dstoff;
                const uint4* p;
                uint32_t sz;
                if (isA) {
                    p = (s < ns0) ? srcA0 + (size_t)s * 64
                                  : srcA1 + (size_t)(s - ns0) * 64;
                    sz = 16u;
                } else {
                    p = (s < ns0) ? srcB0 + (size_t)s * 32
                                  : srcB1 + (size_t)(s - ns0) * 32;
                    sz = bsz;
                }
                cpasync16(d, p, sz);
            }
            CP_COMMIT();
        };

        __syncthreads();
        ldg2(0, q2a, q3a);
        ldg2(1, q2b, q3b);
        issue(0); issue(1); issue(2); issue(3); issue(4);

        #pragma unroll 2
        for (int s = 0; s < ns; s++) {
            CP_WAIT4();
            __syncthreads();

            const uint32_t sb = smb + (uint32_t)(s & 7) * 8192u;
            const uint32_t aaddr = sb + (uint32_t)(warp_m << 10) + (uint32_t)(lane << 4);
            uint4 ah = lds128(aaddr);
            uint4 al = lds128(aaddr + 512u);
            uint4 b0 = lds128(sb + 4096u + (uint32_t)(warp_n << 10) + (uint32_t)(lane << 4));
            uint4 b1 = lds128(sb + 4096u + (uint32_t)(warp_n << 10) + 512u + (uint32_t)(lane << 4));
            const uint4 q2 = (s & 1) ? q2b : q2a;
            const uint4 q3 = (s & 1) ? q3b : q3a;

            uint32_t A_[4] = { ah.x, ah.y, ah.z, ah.w };
            uint32_t L_[4] = { al.x, al.y, al.z, al.w };
            mma16(acc[0], A_, b0.x, b0.y);
            mma16(acc[1], A_, b1.x, b1.y);
            mma16(acc[2], A_, q2.x, q2.y);
            mma16(acc[3], A_, q3.x, q3.y);
            mma16(acc[0], A_, b0.z, b0.w);
            mma16(acc[1], A_, b1.z, b1.w);
            mma16(acc[2], A_, q2.z, q2.w);
            mma16(acc[3], A_, q3.z, q3.w);
            mma16(acc[0], L_, b0.x, b0.y);
            mma16(acc[1], L_, b1.x, b1.y);
            mma16(acc[2], L_, q2.x, q2.y);
            mma16(acc[3], L_, q3.x, q3.y);

            if (s & 1) ldg2(s + 2, q2b, q3b);
            else       ldg2(s + 2, q2a, q3a);
            issue(s + 5);
        }

        if (epi == 2) {
            // fused LSTM cell. nt == gate (i,f,g,o). Thread owns cells
            // (r0,u0) (r0,u0+1) (r1,u0) (r1,u0+1).
            #pragma unroll
            for (int nt = 0; nt < 4; nt++) {
                const float2 bb = *(const float2*)(bias + (ngb + nt) * 8 + 2 * tg);
                acc[nt][0] += bb.x; acc[nt][1] += bb.y;
                acc[nt][2] += bb.x; acc[nt][3] += bb.y;
            }
            const int ub = (n0 >> 5) + warp_n;
            const int u0 = ub * 8 + 2 * tg;
            const int r0 = m0 + warp_m * 16 + g, r1 = r0 + 8;
            float* cst = g_c + (size_t)layer * BH;
            float* hst = g_h + (size_t)layer * BH;
            const float mr0 = 1.f - (float)done_t[r0];
            const float mr1 = 1.f - (float)done_t[r1];
            float2 cp0 = *(float2*)(cst + (size_t)r0 * HID + u0);
            float2 cp1 = *(float2*)(cst + (size_t)r1 * HID + u0);
            float c00 = sigm(acc[1][0]) * (cp0.x * mr0) + sigm(acc[0][0]) * tanhf(acc[2][0]);
            float c01 = sigm(acc[1][1]) * (cp0.y * mr0) + sigm(acc[0][1]) * tanhf(acc[2][1]);
            float c10 = sigm(acc[1][2]) * (cp1.x * mr1) + sigm(acc[0][2]) * tanhf(acc[2][2]);
            float c11 = sigm(acc[1][3]) * (cp1.y * mr1) + sigm(acc[0][3]) * tanhf(acc[2][3]);
            float h00 = sigm(acc[3][0]) * tanhf(c00);
            float h01 = sigm(acc[3][1]) * tanhf(c01);
            float h10 = sigm(acc[3][2]) * tanhf(c10);
            float h11 = sigm(acc[3][3]) * tanhf(c11);
            *(float2*)(cst + (size_t)r0 * HID + u0) = make_float2(c00, c01);
            *(float2*)(cst + (size_t)r1 * HID + u0) = make_float2(c10, c11);
            *(float2*)(hst + (size_t)r0 * HID + u0) = make_float2(h00, h01);
            *(float2*)(hst + (size_t)r1 * HID + u0) = make_float2(h10, h11);
            if (hs_out) {
                *(float2*)(hs_out + (size_t)r0 * HID + u0) = make_float2(h00, h01);
                *(float2*)(hs_out + (size_t)r1 * HID + u0) = make_float2(h10, h11);
            }
            const int sf = ub >> 1, kh = ub & 1;
            const size_t fo = ((size_t)(mg0 + warp_m) * 64 + sf) * 64 + lane * 2;
            uint32_t lo01, lo23;
            uint32_t hi01 = bfsplit(h00, h01, lo01);
            uint32_t hi23 = bfsplit(h10, h11, lo23);
            if (pk_u) {
                char* bp = (char*)(pk_u + fo);
                *(uint2*)(bp + kh * 8)      = make_uint2(hi01, hi23);
                *(uint2*)(bp + 16 + kh * 8) = make_uint2(lo01, lo23);
            }
            if (pk_m) {
                const uint32_t k0 = done_next[r0] ? 0u : 0xFFFFFFFFu;
                const uint32_t k1 = done_next[r1] ? 0u : 0xFFFFFFFFu;
                char* bp = (char*)(pk_m + fo);
                *(uint2*)(bp + kh * 8)      = make_uint2(hi01 & k0, hi23 & k1);
                *(uint2*)(bp + 16 + kh * 8) = make_uint2(lo01 & k0, lo23 & k1);
            }
        } else {
            #pragma unroll
            for (int nt = 0; nt < 4; nt++) {
                const int ng = ngb + nt;
                if (ng * 8 >= N) continue;
                const int c = n0 + warp_n * 32 + nt * 8 + 2 * tg;
                float b0v = bias ? bias[c]     : 0.f;
                float b1v = bias ? bias[c + 1] : 0.f;
                float v0 = acc[nt][0] + b0v, v1 = acc[nt][1] + b1v;
                float v2_ = acc[nt][2] + b0v, v3_ = acc[nt][3] + b1v;
                if (act) {
                    v0  = v0  > 0.f ? v0  : expm1f(v0);
                    v1  = v1  > 0.f ? v1  : expm1f(v1);
                    v2_ = v2_ > 0.f ? v2_ : expm1f(v2_);
                    v3_ = v3_ > 0.f ? v3_ : expm1f(v3_);
                }
                if (epi == 1) {
                    const int sOut = ng >> 1, kh = ng & 1;
                    const int mgA = mg0 + warp_m;
                    uint32_t l01, l23;
                    uint32_t h01 = bfsplit(v0, v1, l01);
                    uint32_t h23 = bfsplit(v2_, v3_, l23);
                    char* bp = (char*)(Cp + ((size_t)mgA * nsCp + sOut) * 64 + lane * 2);
                    *(uint2*)(bp + kh * 8)      = make_uint2(h01, h23);
                    *(uint2*)(bp + 16 + kh * 8) = make_uint2(l01, l23);
                } else {
                    const int rr = m0 + warp_m * 16 + g;
                    *(float2*)(C + (size_t)rr * ldc + c)       = make_float2(v0, v1);
                    *(float2*)(C + (size_t)(rr + 8) * ldc + c) = make_float2(v2_, v3_);
                }
            }
        }
    }
}

// initial pack: h_init * mask0 -> h0m[0] / h1m[0], plus fp32 h/c copy
__device__ void init_phase(const float* __restrict__ h0in,
                           const float* __restrict__ c0in,
                           const int* __restrict__ done0)
{
    const int gt = blockIdx.x * NTHR + threadIdx.x;
    for (int i = gt; i < 2 * BH; i += NBLK * NTHR) { g_h[i] = h0in[i]; g_c[i] = c0in[i]; }

    const int mi = gt >> 15, fx = gt & 32767;
    const int lane = fx & 31, s = (fx >> 5) & 63, mg = fx >> 11;
    const int g = lane >> 2, tg = lane & 3;
    const int b0 = mg * 16 + g, b1 = b0 + 8;
    const int c0 = s * 16 + 2 * tg;
    const float m0r = 1.f - (float)done0[b0];
    const float m1r = 1.f - (float)done0[b1];
    const float* p0 = h0in + (size_t)mi * BH + (size_t)b0 * HID + c0;
    const float* p1 = h0in + (size_t)mi * BH + (size_t)b1 * HID + c0;
    uint32_t l0, l1, l2, l3;
    uint32_t a0 = bfsplit(p0[0] * m0r, p0[1] * m0r, l0);
    uint32_t a1 = bfsplit(p1[0] * m1r, p1[1] * m1r, l1);
    uint32_t a2 = bfsplit(p0[8] * m0r, p0[9] * m0r, l2);
    uint32_t a3 = bfsplit(p1[8] * m1r, p1[9] * m1r, l3);
    uint4* d = (mi ? g_h1m[0] : g_h0m[0]) + ((size_t)mg * 64 + s) * 64 + lane * 2;
    d[0] = make_uint4(a0, a1, a2, a3);
    d[1] = make_uint4(l0, l1, l2, l3);
}

__device__ void layernorm_pack(const float* __restrict__ gamma,
                               const float* __restrict__ beta)
{
    const int mg = (blockIdx.x * NTHR + threadIdx.x) >> 5;
    const int lane = threadIdx.x & 31;
    const int g = lane >> 2, tg = lane & 3;
    const float* r0 = g_hs + ((size_t)mg * 16 + g) * HID;
    const float* r1 = r0 + (size_t)8 * HID;

    float s0 = 0.f, ss0 = 0.f, s1 = 0.f, ss1 = 0.f;
    for (int s = 0; s < 64; s++) {
        const int c = s * 16 + 2 * tg;
        float2 a = *(const float2*)(r0 + c), b = *(const float2*)(r0 + c + 8);
        float2 d = *(const float2*)(r1 + c), e = *(const float2*)(r1 + c + 8);
        s0 += a.x + a.y + b.x + b.y;  ss0 += a.x*a.x + a.y*a.y + b.x*b.x + b.y*b.y;
        s1 += d.x + d.y + e.x + e.y;  ss1 += d.x*d.x + d.y*d.y + e.x*e.x + e.y*e.y;
    }
    #pragma unroll
    for (int o = 1; o <= 2; o <<= 1) {
        s0  += __shfl_xor_sync(0xffffffffu, s0, o);
        ss0 += __shfl_xor_sync(0xffffffffu, ss0, o);
        s1  += __shfl_xor_sync(0xffffffffu, s1, o);
        ss1 += __shfl_xor_sync(0xffffffffu, ss1, o);
    }
    const float mu0 = s0 * (1.f/HID), mu1 = s1 * (1.f/HID);
    const float rs0 = rsqrtf(ss0 * (1.f/HID) - mu0*mu0 + 1e-5f);
    const float rs1 = rsqrtf(ss1 * (1.f/HID) - mu1*mu1 + 1e-5f);

    uint4* dst = g_hsp + (size_t)mg * 64 * 64 + lane * 2;
    for (int s = 0; s < 64; s++) {
        const int c = s * 16 + 2 * tg;
        float2 a = *(const float2*)(r0 + c), b = *(const float2*)(r0 + c + 8);
        float2 d = *(const float2*)(r1 + c), e = *(const float2*)(r1 + c + 8);
        float2 gc = *(const float2*)(gamma + c), gc8 = *(const float2*)(gamma + c + 8);
        float2 bc = *(const float2*)(beta + c),  bc8 = *(const float2*)(beta + c + 8);
        float n00 = (a.x - mu0) * rs0 * gc.x  + bc.x,  n01 = (a.y - mu0) * rs0 * gc.y  + bc.y;
        float n02 = (b.x - mu0) * rs0 * gc8.x + bc8.x, n03 = (b.y - mu0) * rs0 * gc8.y + bc8.y;
        float n10 = (d.x - mu1) * rs1 * gc.x  + bc.x,  n11 = (d.y - mu1) * rs1 * gc.y  + bc.y;
        float n12 = (e.x - mu1) * rs1 * gc8.x + bc8.x, n13 = (e.y - mu1) * rs1 * gc8.y + bc8.y;
        uint32_t l0, l1, l2, l3;
        uint32_t a0 = bfsplit(n00, n01, l0);
        uint32_t a1 = bfsplit(n10, n11, l1);
        uint32_t a2 = bfsplit(n02, n03, l2);
        uint32_t a3 = bfsplit(n12, n13, l3);
        dst[(size_t)s * 64]     = make_uint4(a0, a1, a2, a3);
        dst[(size_t)s * 64 + 1] = make_uint4(l0, l1, l2, l3);
    }
}

__global__ __launch_bounds__(NTHR)
void critic_kernel(
    const int* __restrict__ done,
    const float* __restrict__ h0, const float* __restrict__ c0,
    const float* __restrict__ lng,  const float* __restrict__ lnb,
    const float* __restrict__ b1,   const float* __restrict__ b2,
    const float* __restrict__ b3,
    const float* __restrict__ Wv,   const float* __restrict__ bv,
    float* __restrict__ out, int out_size)
{
    extern __shared__ char smdyn[];
    const int stride = NBLK * NTHR;
    const int gtid = blockIdx.x * NTHR + threadIdx.x;

    init_phase(h0, c0, done);
    grid_sync();

    for (int t = 0; t < SEQ; ++t) {
        const int* dt = done + t * BATCH;
        const int* dn = (t + 1 < SEQ) ? done + (t + 1) * BATCH : nullptr;
        const int pb = t & 1, pn = (t + 1) & 1;

        gemm_mma(smdyn, BATCH, GATES,
                 g_xpack + (size_t)t * 4096, 4, g_h0m[pb], 64,
                 pk_ih0, pk_hh0, g_bias0,
                 nullptr, 0, 0, nullptr, 0,
                 2, 0, dt, g_h0u, dn ? g_h0m[pn] : nullptr, dn, nullptr);
        grid_sync();

        gemm_mma(smdyn, BATCH, GATES,
                 g_h0u, 64, g_h1m[pb], 64,
                 pk_ih1, pk_hh1, g_bias1,
                 nullptr, 0, 0, nullptr, 0,
                 2, 1, dt, nullptr, dn ? g_h1m[pn] : nullptr, dn,
                 g_hs + (size_t)t * BH);
        grid_sync();
    }

    layernorm_pack(lng, lnb);
    grid_sync();

    gemm_mma(smdyn, SEQ * BATCH, 512, g_hsp, 64, nullptr, 0,
             pk_W1, nullptr, b1, nullptr, 0, 1, g_a1p, 32,
             1, 0, nullptr, nullptr, nullptr, nullptr, nullptr);
    grid_sync();
    gemm_mma(smdyn, SEQ * BATCH, 128, g_a1p, 32, nullptr, 0,
             pk_W2, nullptr, b2, nullptr, 0, 1, g_a2p, 8,
             1, 0, nullptr, nullptr, nullptr, nullptr, nullptr);
    grid_sync();
    gemm_mma(smdyn, SEQ * BATCH, 64, g_a2p, 8, nullptr, 0,
             pk_W3, nullptr, b3, g_a3, 64, 1, nullptr, 0,
             0, 0, nullptr, nullptr, nullptr, nullptr, nullptr);
    grid_sync();

    for (int r = gtid; r < SEQ * BATCH; r += stride) {
        const float* a = g_a3 + (size_t)r * 64;
        float s = bv[0];
        #pragma unroll
        for (int k = 0; k < 64; k++) s += a[k] * Wv[k];
        out[r] = s;
    }
    if (out_size >= SEQ * BATCH + 4 * BH) {
        float* oh = out + SEQ * BATCH;
        float* oc = oh + 2 * BH;
        for (int i = gtid; i < 2 * BH; i += stride) {
            oh[i] = g_h[i];
            oc[i] = g_c[i];
        }
    }
}

extern "C" void kernel_launch(void* const* d_in, const int* in_sizes, int n_in,
                              void* d_out, int out_size)
{
    prepack_kernel<<<NBLK, NTHR>>>(
        (const float*)d_in[4],  (const float*)d_in[5],
        (const float*)d_in[8],  (const float*)d_in[9],
        (const float*)d_in[14], (const float*)d_in[16],
        (const float*)d_in[18], (const float*)d_in[0],
        (const float*)d_in[6],  (const float*)d_in[7],
        (const float*)d_in[10], (const float*)d_in[11]);
    cudaFuncSetAttribute(critic_kernel,
                         cudaFuncAttributeMaxDynamicSharedMemorySize, 65536);
    critic_kernel<<<NBLK, NTHR, 65536>>>(
        (const int*)d_in[1],
        (const float*)d_in[2],  (const float*)d_in[3],
        (const float*)d_in[12], (const float*)d_in[13],
        (const float*)d_in[15], (const float*)d_in[17],
        (const float*)d_in[19],
        (const float*)d_in[20], (const float*)d_in[21],
        (float*)d_out, out_size);
}

// round 17
// speedup vs baseline: 1.4533x; 1.4533x over previous
#include <cuda_runtime.h>
#include <cstdint>
#include <cstddef>

#define SEQ   128
#define BATCH 256
#define OBS   64
#define HID   1024
#define GATES 4096
#define NBLK  128
#define NTHR  512
#define BH    (BATCH * HID)

// ---- fp32 scratch ----
__device__ float g_h[2 * BH];
__device__ float g_c[2 * BH];
__device__ float g_gates[BATCH * GATES];
__device__ float g_hs[(size_t)SEQ * BH];
__device__ float g_a3[(size_t)SEQ * BATCH * 64];

// ---- packed B (weights): uint4 {hi.r0,hi.r1,lo.r0,lo.r1} per lane per (n8,k16) frag
__device__ uint4 pk_ih0[(size_t)2048  * 32];
__device__ uint4 pk_hh0[(size_t)32768 * 32];
__device__ uint4 pk_ih1[(size_t)32768 * 32];
__device__ uint4 pk_hh1[(size_t)32768 * 32];
__device__ uint4 pk_W1 [(size_t)4096  * 32];
__device__ uint4 pk_W2 [(size_t)512   * 32];
__device__ uint4 pk_W3 [(size_t)64    * 32];

// ---- packed A (activations) ----
__device__ uint4 g_xpack[(size_t)8192 * 64];
__device__ uint4 g_h0m [(size_t)1024 * 64];
__device__ uint4 g_h0u [(size_t)1024 * 64];
__device__ uint4 g_h1m [(size_t)1024 * 64];
__device__ uint4 g_hsp [(size_t)131072 * 64];
__device__ uint4 g_a1p [(size_t)65536 * 64];
__device__ uint4 g_a2p [(size_t)16384 * 64];

// ---- grid barrier ----
__device__ unsigned g_arr = 0;
__device__ volatile unsigned g_rel = 0;

__device__ __forceinline__ void grid_sync() {
    __syncthreads();
    if (threadIdx.x == 0) {
        __threadfence();
        unsigned v = atomicAdd(&g_arr, 1u);
        unsigned target = v / NBLK + 1u;
        if ((v % NBLK) == NBLK - 1u) g_rel = target;
        else while (g_rel < target) { }
        __threadfence();
    }
    __syncthreads();
}

__device__ __forceinline__ float sigm(float x) { return 1.0f / (1.0f + expf(-x)); }

__device__ __forceinline__ uint32_t smem_u32_of(const void* p) {
    uint32_t a;
    asm("{ .reg .u64 t; cvta.to.shared.u64 t, %1; cvt.u32.u64 %0, t; }" : "=r"(a) : "l"(p));
    return a;
}
__device__ __forceinline__ uint4 lds128(uint32_t a) {
    uint4 v;
    asm volatile("ld.shared.v4.u32 {%0,%1,%2,%3}, [%4];"
                 : "=r"(v.x), "=r"(v.y), "=r"(v.z), "=r"(v.w) : "r"(a));
    return v;
}
__device__ __forceinline__ void cpasync16(uint32_t dst, const void* src, uint32_t sz) {
    asm volatile("cp.async.cg.shared.global [%0], [%1], 16, %2;"
                 :: "r"(dst), "l"(src), "r"(sz) : "memory");
}
#define CP_COMMIT() asm volatile("cp.async.commit_group;" ::: "memory")
#define CP_WAIT4()  asm volatile("cp.async.wait_group 4;" ::: "memory")

// pack (x0,x1) -> bf16x2 hi (x0 low), lo of residuals
__device__ __forceinline__ uint32_t bfsplit(float x0, float x1, uint32_t& lo) {
    uint32_t h;
    asm("cvt.rn.bf16x2.f32 %0, %1, %2;" : "=r"(h) : "f"(x1), "f"(x0));
    float h0 = __uint_as_float(h << 16);
    float h1 = __uint_as_float(h & 0xFFFF0000u);
    float l0 = x0 - h0, l1 = x1 - h1;
    asm("cvt.rn.bf16x2.f32 %0, %1, %2;" : "=r"(lo) : "f"(l1), "f"(l0));
    return h;
}
__device__ __forceinline__ void mma16(float d[4], const uint32_t a[4],
                                      uint32_t b0, uint32_t b1) {
    asm("mma.sync.aligned.m16n8k16.row.col.f32.bf16.bf16.f32 "
        "{%0,%1,%2,%3}, {%4,%5,%6,%7}, {%8,%9}, {%0,%1,%2,%3};"
        : "+f"(d[0]), "+f"(d[1]), "+f"(d[2]), "+f"(d[3])
        : "r"(a[0]), "r"(a[1]), "r"(a[2]), "r"(a[3]), "r"(b0), "r"(b1));
}

// ---- prepack ----
#define NWFRAG 105024
#define NFRAG  (NWFRAG + 8192)
__global__ __launch_bounds__(NTHR) void prepack_kernel(
    const float* __restrict__ Wih0, const float* __restrict__ Whh0,
    const float* __restrict__ Wih1, const float* __restrict__ Whh1,
    const float* __restrict__ W1,  const float* __restrict__ W2,
    const float* __restrict__ W3,  const float* __restrict__ x)
{
    const int total = NFRAG * 32;
    for (int t = blockIdx.x * blockDim.x + threadIdx.x; t < total;
         t += gridDim.x * blockDim.x) {
        const int f = t >> 5, lane = t & 31;
        const int g = lane >> 2, tig = lane & 3;
        if (f < NWFRAG) {
            const float* W; uint4* pk; int ns, K, fl;
            if      (f < 2048)   { W = Wih0; pk = pk_ih0; ns = 4;  K = 64;   fl = f; }
            else if (f < 34816)  { W = Whh0; pk = pk_hh0; ns = 64; K = 1024; fl = f - 2048; }
            else if (f < 67584)  { W = Wih1; pk = pk_ih1; ns = 64; K = 1024; fl = f - 34816; }
            else if (f < 100352) { W = Whh1; pk = pk_hh1; ns = 64; K = 1024; fl = f - 67584; }
            else if (f < 104448) { W = W1;   pk = pk_W1;  ns = 64; K = 1024; fl = f - 100352; }
            else if (f < 104960) { W = W2;   pk = pk_W2;  ns = 32; K = 512;  fl = f - 104448; }
            else                 { W = W3;   pk = pk_W3;  ns = 8;  K = 128;  fl = f - 104960; }
            const int ng = fl / ns, s = fl - ng * ns;
            const float* wp = W + (size_t)(ng * 8 + g) * K + s * 16 + 2 * tig;
            uint32_t l01, l23;
            uint32_t h01 = bfsplit(wp[0], wp[1], l01);
            uint32_t h23 = bfsplit(wp[8], wp[9], l23);
            pk[(size_t)fl * 32 + lane] = make_uint4(h01, h23, l01, l23);
        } else {
            const int fx = f - NWFRAG;
            const int ts = fx >> 6, mg = (fx >> 2) & 15, s = fx & 3;
            const int r0 = ts * 256 + mg * 16 + g, r1 = r0 + 8;
            const int c0 = s * 16 + 2 * tig;
            const float* p0 = x + (size_t)r0 * OBS + c0;
            const float* p1 = x + (size_t)r1 * OBS + c0;
            uint32_t l0, l1, l2, l3;
            uint32_t a0 = bfsplit(p0[0], p0[1], l0);
            uint32_t a1 = bfsplit(p1[0], p1[1], l1);
            uint32_t a2 = bfsplit(p0[8], p0[9], l2);
            uint32_t a3 = bfsplit(p1[8], p1[9], l3);
            uint4* d = g_xpack + (size_t)fx * 64 + lane * 2;
            d[0] = make_uint4(a0, a1, a2, a3);
            d[1] = make_uint4(l0, l1, l2, l3);
        }
    }
}

// GEMM: 8-stage cp.async smem pipeline (A + B[nt0,1]), 2 slabs per
// wait+syncthreads; 2-deep LDG register pipeline (B[nt2,3]).
// CTA 64x128, 16 warps (4m x 4n), warp 16x32. All ns used are even.
__device__ void gemm_mma(char* smdyn, int M, int N,
                         const uint4* __restrict__ Af0, int ns0,
                         const uint4* __restrict__ Af1, int ns1,
                         const uint4* __restrict__ PK0,
                         const uint4* __restrict__ PK1,
                         const float* __restrict__ bias0,
                         const float* __restrict__ bias1,
                         float* __restrict__ C, int ldc, int act,
                         uint4* __restrict__ Cp, int nsCp)
{
    const uint32_t smb = smem_u32_of(smdyn);
    const int tid = threadIdx.x, lane = tid & 31, wid = tid >> 5;
    const int warp_m = wid & 3, warp_n = wid >> 2;
    const int g = lane >> 2, tg = lane & 3;
    const int ns = ns0 + ns1;
    const int ntm = M / 64, ntn = (N + 127) / 128;

    const bool isA = tid < 256;
    uint32_t dstoff; int mgl = 0, eA = 0, ngl = 0, eB = 0;
    if (isA) {
        mgl = tid >> 6; eA = tid & 63;
        dstoff = (uint32_t)(mgl * 1024 + (eA & 1) * 512 + (eA >> 1) * 16);
    } else {
        const int j = tid - 256;
        const int fr = j >> 5; eB = j & 31;
        ngl = (fr >> 1) * 4 + (fr & 1);
        dstoff = (uint32_t)(4096 + fr * 512 + eB * 16);
    }

    for (int u = blockIdx.x; u < ntm * ntn; u += NBLK) {
        const int m0 = (u % ntm) * 64, n0 = (u / ntm) * 128;
        const int mg0 = m0 >> 4;
        const int ngb = (n0 >> 3) + warp_n * 4;

        const uint4* srcA0 = nullptr; const uint4* srcA1 = nullptr;
        const uint4* srcB0 = nullptr; const uint4* srcB1 = nullptr;
        uint32_t bsz = 16;
        if (isA) {
            const int mgA = mg0 + mgl;
            srcA0 = Af0 + (size_t)mgA * ns0 * 64 + eA;
            if (Af1) srcA1 = Af1 + (size_t)mgA * ns1 * 64 + eA;
        } else {
            const int ngT = (n0 >> 3) + ngl;
            const bool bv = ngT * 8 < N;
            bsz = bv ? 16u : 0u;
            srcB0 = PK0 + (bv ? (size_t)ngT * ns0 * 32 : 0) + eB;
            if (PK1) srcB1 = PK1 + (bv ? (size_t)ngT * ns1 * 32 : 0) + eB;
        }
        const int ng2 = ngb + 2, ng3 = ngb + 3;
        const bool v2 = ng2 * 8 < N, v3 = ng3 * 8 < N;
        const uint4* pB2_0 = PK0 + (v2 ? (size_t)ng2 * ns0 * 32 : 0) + lane;
        const uint4* pB3_0 = PK0 + (v3 ? (size_t)ng3 * ns0 * 32 : 0) + lane;
        const uint4* pB2_1 = PK1 ? PK1 + (v2 ? (size_t)ng2 * ns1 * 32 : 0) + lane : nullptr;
        const uint4* pB3_1 = PK1 ? PK1 + (v3 ? (size_t)ng3 * ns1 * 32 : 0) + lane : nullptr;

        float acc[4][4];
        #pragma unroll
        for (int i = 0; i < 4; i++)
            #pragma unroll
            for (int j2 = 0; j2 < 4; j2++) acc[i][j2] = 0.f;

        uint4 q2a = make_uint4(0,0,0,0), q3a = q2a, q2b = q2a, q3b = q2a;

        auto ldg2 = [&](int s, uint4& q2, uint4& q3) {
            if (s >= ns) return;
            if (s < ns0) {
                if (v2) q2 = pB2_0[(size_t)s * 32];
                if (v3) q3 = pB3_0[(size_t)s * 32];
            } else {
                if (v2) q2 = pB2_1[(size_t)(s - ns0) * 32];
                if (v3) q3 = pB3_1[(size_t)(s - ns0) * 32];
            }
        };
        auto issue = [&](int s) {
            if (s < ns) {
                const uint32_t d = smb + (uint32_t)(s & 7) * 8192u + dstoff;
                const uint4* p;
                uint32_t sz;
                if (isA) {
                    p = (s < ns0) ? srcA0 + (size_t)s * 64
                                  : srcA1 + (size_t)(s - ns0) * 64;
                    sz = 16u;
                } else {
                    p = (s < ns0) ? srcB0 + (size_t)s * 32
                                  : srcB1 + (size_t)(s - ns0) * 32;
                    sz = bsz;
                }
                cpasync16(d, p, sz);
            }
            CP_COMMIT();
        };
        auto slab = [&](int s, const uint4& q2, const uint4& q3) {
            const uint32_t sb = smb + (uint32_t)(s & 7) * 8192u;
            const uint32_t aaddr = sb + (uint32_t)(warp_m << 10) + (uint32_t)(lane << 4);
            uint4 ah = lds128(aaddr);
            uint4 al = lds128(aaddr + 512u);
            uint4 b0 = lds128(sb + 4096u + (uint32_t)(warp_n << 10) + (uint32_t)(lane << 4));
            uint4 b1 = lds128(sb + 4096u + (uint32_t)(warp_n << 10) + 512u + (uint32_t)(lane << 4));
            uint32_t A_[4] = { ah.x, ah.y, ah.z, ah.w };
            uint32_t L_[4] = { al.x, al.y, al.z, al.w };
            mma16(acc[0], A_, b0.x, b0.y);
            mma16(acc[1], A_, b1.x, b1.y);
            mma16(acc[2], A_, q2.x, q2.y);
            mma16(acc[3], A_, q3.x, q3.y);
            mma16(acc[0], A_, b0.z, b0.w);
            mma16(acc[1], A_, b1.z, b1.w);
            mma16(acc[2], A_, q2.z, q2.w);
            mme_tail:
            mma16(acc[3], A_, q3.z, q3.w);
            mma16(acc[0], L_, b0.x, b0.y);
            mma16(acc[1], L_, b1.x, b1.y);
            mma16(acc[2], L_, q2.x, q2.y);
            mma16(acc[3], L_, q3.x, q3.y);
        };

        __syncthreads();            // previous unit's smem fully consumed
        ldg2(0, q2a, q3a);
        ldg2(1, q2b, q3b);
        issue(0); issue(1); issue(2); issue(3); issue(4); issue(5);

        for (int s = 0; s < ns; s += 2) {
            CP_WAIT4();
            __syncthreads();
            // slab s (even -> qa)
            slab(s, q2a, q3a);
            ldg2(s + 2, q2a, q3a);
            issue(s + 6);
            // slab s+1 (odd -> qb)
            slab(s + 1, q2b, q3b);
            ldg2(s + 3, q2b, q3b);
            issue(s + 7);
        }

        // epilogue
        #pragma unroll
        for (int nt = 0; nt < 4; nt++) {
            const int ng = ngb + nt;
            if (ng * 8 >= N) continue;
            const int c = n0 + warp_n * 32 + nt * 8 + 2 * tg;
            float b0v = bias0 ? bias0[c]     : 0.f;
            float b1v = bias0 ? bias0[c + 1] : 0.f;
            if (bias1) { b0v += bias1[c]; b1v += bias1[c + 1]; }
            float v0 = acc[nt][0] + b0v, v1 = acc[nt][1] + b1v;
            float v2_ = acc[nt][2] + b0v, v3_ = acc[nt][3] + b1v;
            if (act) {
                v0  = v0  > 0.f ? v0  : expm1f(v0);
                v1  = v1  > 0.f ? v1  : expm1f(v1);
                v2_ = v2_ > 0.f ? v2_ : expm1f(v2_);
                v3_ = v3_ > 0.f ? v3_ : expm1f(v3_);
            }
            if (Cp) {
                const int sOut = ng >> 1, kh = ng & 1;
                const int mgA = mg0 + warp_m;
                uint32_t l01, l23;
                uint32_t h01 = bfsplit(v0, v1, l01);
                uint32_t h23 = bfsplit(v2_, v3_, l23);
                char* bp = (char*)(Cp + ((size_t)mgA * nsCp + sOut) * 64 + lane * 2);
                *(uint2*)(bp + kh * 8)      = make_uint2(h01, h23);
                *(uint2*)(bp + 16 + kh * 8) = make_uint2(l01, l23);
            } else {
                const int rr = m0 + warp_m * 16 + g;
                *(float2*)(C + (size_t)rr * ldc + c)       = make_float2(v0, v1);
                *(float2*)(C + (size_t)(rr + 8) * ldc + c) = make_float2(v2_, v3_);
            }
        }
    }
}

// LSTM cell
__device__ void cell_phase(int layer, const int* __restrict__ done_t,
                           const int* __restrict__ done_next,
                           float* __restrict__ hs_out,
                           uint4* __restrict__ pk_u, uint4* __restrict__ pk_m)
{
    const int gt = blockIdx.x * NTHR + threadIdx.x;
    const int lane = gt & 31, kh = (gt >> 5) & 1, s = (gt >> 6) & 63, mg = gt >> 12;
    const int g = lane >> 2, tg = lane & 3;
    const int b0 = mg * 16 + g, b1 = b0 + 8;
    const int j = s * 16 + kh * 8 + 2 * tg;

    const float* gp0 = g_gates + (size_t)b0 * GATES + j;
    const float* gp1 = g_gates + (size_t)b1 * GATES + j;
    float2 i0 = *(const float2*)gp0,          i1 = *(const float2*)gp1;
    float2 f0 = *(const float2*)(gp0 + 1024), f1 = *(const float2*)(gp1 + 1024);
    float2 q0 = *(const float2*)(gp0 + 2048), q1 = *(const float2*)(gp1 + 2048);
    float2 o0 = *(const float2*)(gp0 + 3072), o1 = *(const float2*)(gp1 + 3072);

    float* cst = g_c + (size_t)layer * BH;
    float* hst = g_h + (size_t)layer * BH;
    const float m0r = 1.f - (float)done_t[b0];
    const float m1r = 1.f - (float)done_t[b1];
    float2 c0v = *(float2*)(cst + (size_t)b0 * HID + j);
    float2 c1v = *(float2*)(cst + (size_t)b1 * HID + j);

    float c00 = sigm(f0.x) * (c0v.x * m0r) + sigm(i0.x) * tanhf(q0.x);
    float c01 = sigm(f0.y) * (c0v.y * m0r) + sigm(i0.y) * tanhf(q0.y);
    float c10 = sigm(f1.x) * (c1v.x * m1r) + sigm(i1.x) * tanhf(q1.x);
    float c11 = sigm(f1.y) * (c1v.y * m1r) + sigm(i1.y) * tanhf(q1.y);
    float h00 = sigm(o0.x) * tanhf(c00), h01 = sigm(o0.y) * tanhf(c01);
    float h10 = sigm(o1.x) * tanhf(c10), h11 = sigm(o1.y) * tanhf(c11);

    *(float2*)(cst + (size_t)b0 * HID + j) = make_float2(c00, c01);
    *(float2*)(cst + (size_t)b1 * HID + j) = make_float2(c10, c11);
    *(float2*)(hst + (size_t)b0 * HID + j) = make_float2(h00, h01);
    *(float2*)(hst + (size_t)b1 * HID + j) = make_float2(h10, h11);
    if (hs_out) {
        *(float2*)(hs_out + (size_t)b0 * HID + j) = make_float2(h00, h01);
        *(float2*)(hs_out + (size_t)b1 * HID + j) = make_float2(h10, h11);
    }

    uint32_t lo0, lo1;
    uint32_t hi0 = bfsplit(h00, h01, lo0);
    uint32_t hi1 = bfsplit(h10, h11, lo1);
    const size_t fo = ((size_t)mg * 64 + s) * 64 + lane * 2;
    if (pk_u) {
        char* bp = (char*)(pk_u + fo);
        *(uint2*)(bp + kh * 8)      = make_uint2(hi0, hi1);
        *(uint2*)(bp + 16 + kh * 8) = make_uint2(lo0, lo1);
    }
    if (pk_m && done_next) {
        const uint32_t k0 = done_next[b0] ? 0u : 0xFFFFFFFFu;
        const uint32_t k1 = done_next[b1] ? 0u : 0xFFFFFFFFu;
        char* bp = (char*)(pk_m + fo);
        *(uint2*)(bp + kh * 8)      = make_uint2(hi0 & k0, hi1 & k1);
        *(uint2*)(bp + 16 + kh * 8) = make_uint2(lo0 & k0, lo1 & k1);
    }
}

__device__ void init_phase(const float* __restrict__ h0in,
                           const float* __restrict__ c0in,
                           const int* __restrict__ done0)
{
    const int gt = blockIdx.x * NTHR + threadIdx.x;
    for (int i = gt; i < 2 * BH; i += NBLK * NTHR) { g_h[i] = h0in[i]; g_c[i] = c0in[i]; }

    const int mi = gt >> 15, fx = gt & 32767;
    const int lane = fx & 31, s = (fx >> 5) & 63, mg = fx >> 11;
    const int g = lane >> 2, tg = lane & 3;
    const int b0 = mg * 16 + g, b1 = b0 + 8;
    const int c0 = s * 16 + 2 * tg;
    const float m0r = 1.f - (float)done0[b0];
    const float m1r = 1.f - (float)done0[b1];
    const float* p0 = h0in + (size_t)mi * BH + (size_t)b0 * HID + c0;
    const float* p1 = h0in + (size_t)mi * BH + (size_t)b1 * HID + c0;
    uint32_t l0, l1, l2, l3;
    uint32_t a0 = bfsplit(p0[0] * m0r, p0[1] * m0r, l0);
    uint32_t a1 = bfsplit(p1[0] * m1r, p1[1] * m1r, l1);
    uint32_t a2 = bfsplit(p0[8] * m0r, p0[9] * m0r, l2);
    uint32_t a3 = bfsplit(p1[8] * m1r, p1[9] * m1r, l3);
    uint4* d = (mi ? g_h1m : g_h0m) + ((size_t)mg * 64 + s) * 64 + lane * 2;
    d[0] = make_uint4(a0, a1, a2, a3);
    d[1] = make_uint4(l0, l1, l2, l3);
}

__device__ void layernorm_pack(const float* __restrict__ gamma,
                               const float* __restrict__ beta)
{
    const int mg = (blockIdx.x * NTHR + threadIdx.x) >> 5;
    const int lane = threadIdx.x & 31;
    const int g = lane >> 2, tg = lane & 3;
    const float* r0 = g_hs + ((size_t)mg * 16 + g) * HID;
    const float* r1 = r0 + (size_t)8 * HID;

    float s0 = 0.f, ss0 = 0.f, s1 = 0.f, ss1 = 0.f;
    for (int s = 0; s < 64; s++) {
        const int c = s * 16 + 2 * tg;
        float2 a = *(const float2*)(r0 + c), b = *(const float2*)(r0 + c + 8);
        float2 d = *(const float2*)(r1 + c), e = *(const float2*)(r1 + c + 8);
        s0 += a.x + a.y + b.x + b.y;  ss0 += a.x*a.x + a.y*a.y + b.x*b.x + b.y*b.y;
        s1 += d.x + d.y + e.x + e.y;  ss1 += d.x*d.x + d.y*d.y + e.x*e.x + e.y*e.y;
    }
    #pragma unroll
    for (int o = 1; o <= 2; o <<= 1) {
        s0  += __shfl_xor_sync(0xffffffffu, s0, o);
        ss0 += __shfl_xor_sync(0xffffffffu, ss0, o);
        s1  += __shfl_xor_sync(0xffffffffu, s1, o);
        ss1 += __shfl_xor_sync(0xffffffffu, ss1, o);
    }
    const float mu0 = s0 * (1.f/HID), mu1 = s1 * (1.f/HID);
    const float rs0 = rsqrtf(ss0 * (1.f/HID) - mu0*mu0 + 1e-5f);
    const float rs1 = rsqrtf(ss1 * (1.f/HID) - mu1*mu1 + 1e-5f);

    uint4* dst = g_hsp + (size_t)mg * 64 * 64 + lane * 2;
    for (int s = 0; s < 64; s++) {
        const int c = s * 16 + 2 * tg;
        float2 a = *(const float2*)(r0 + c), b = *(const float2*)(r0 + c + 8);
        float2 d = *(const float2*)(r1 + c), e = *(const float2*)(r1 + c + 8);
        float2 gc = *(const float2*)(gamma + c), gc8 = *(const float2*)(gamma + c + 8);
        float2 bc = *(const float2*)(beta + c),  bc8 = *(const float2*)(beta + c + 8);
        float n00 = (a.x - mu0) * rs0 * gc.x  + bc.x,  n01 = (a.y - mu0) * rs0 * gc.y  + bc.y;
        float n02 = (b.x - mu0) * rs0 * gc8.x + bc8.x, n03 = (b.y - mu0) * rs0 * gc8.y + bc8.y;
        float n10 = (d.x - mu1) * rs1 * gc.x  + bc.x,  n11 = (d.y - mu1) * rs1 * gc.y  + bc.y;
        float n12 = (e.x - mu1) * rs1 * gc8.x + bc8.x, n13 = (e.y - mu1) * rs1 * gc8.y + bc8.y;
        uint32_t l0, l1, l2, l3;
        uint32_t a0 = bfsplit(n00, n01, l0);
        uint32_t a1 = bfsplit(n10, n11, l1);
        uint32_t a2 = bfsplit(n02, n03, l2);
        uint32_t a3 = bfsplit(n12, n13, l3);
        dst[(size_t)s * 64]     = make_uint4(a0, a1, a2, a3);
        dst[(size_t)s * 64 + 1] = make_uint4(l0, l1, l2, l3);
    }
}

__global__ __launch_bounds__(NTHR)
void critic_kernel(
    const float* __restrict__ x, const int* __restrict__ done,
    const float* __restrict__ h0, const float* __restrict__ c0,
    const float* __restrict__ bih0, const float* __restrict__ bhh0,
    const float* __restrict__ bih1, const float* __restrict__ bhh1,
    const float* __restrict__ lng,  const float* __restrict__ lnb,
    const float* __restrict__ b1,   const float* __restrict__ b2,
    const float* __restrict__ b3,
    const float* __restrict__ Wv,   const float* __restrict__ bv,
    float* __restrict__ out, int out_size)
{
    extern __shared__ char smdyn[];
    const int stride = NBLK * NTHR;
    const int gtid = blockIdx.x * NTHR + threadIdx.x;

    init_phase(h0, c0, done);
    grid_sync();

    for (int t = 0; t < SEQ; ++t) {
        const int* dt = done + t * BATCH;
        const int* dn = (t + 1 < SEQ) ? done + (t + 1) * BATCH : nullptr;

        gemm_mma(smdyn, BATCH, GATES,
                 g_xpack + (size_t)t * 4096, 4, g_h0m, 64,
                 pk_ih0, pk_hh0, bih0, bhh0,
                 g_gates, GATES, 0, nullptr, 0);
        grid_sync();
        cell_phase(0, dt, dn, nullptr, g_h0u, g_h0m);
        grid_sync();

        gemm_mma(smdyn, BATCH, GATES,
                 g_h0u, 64, g_h1m, 64,
                 pk_ih1, pk_hh1, bih1, bhh1,
                 g_gates, GATES, 0, nullptr, 0);
        grid_sync();
        cell_phase(1, dt, dn, g_hs + (size_t)t * BH, nullptr, g_h1m);
        grid_sync();
    }

    layernorm_pack(lng, lnb);
    grid_sync();

    gemm_mma(smdyn, SEQ * BATCH, 512, g_hsp, 64, nullptr, 0,
             pk_W1, nullptr, b1, nullptr, nullptr, 0, 1, g_a1p, 32);
    grid_sync();
    gemm_mma(smdyn, SEQ * BATCH, 128, g_a1p, 32, nullptr, 0,
             pk_W2, nullptr, b2, nullptr, nullptr, 0, 1, g_a2p, 8);
    grid_sync();
    gemm_mma(smdyn, SEQ * BATCH, 64, g_a2p, 8, nullptr, 0,
             pk_W3, nullptr, b3, nullptr, g_a3, 64, 1, nullptr, 0);
    grid_sync();

    for (int r = gtid; r < SEQ * BATCH; r += stride) {
        const float* a = g_a3 + (size_t)r * 64;
        float s = bv[0];
        #pragma unroll
        for (int k = 0; k < 64; k++) s += a[k] * Wv[k];
        out[r] = s;
    }
    if (out_size >= SEQ * BATCH + 4 * BH) {
        float* oh = out + SEQ * BATCH;
        float* oc = oh + 2 * BH;
        for (int i = gtid; i < 2 * BH; i += stride) {
            oh[i] = g_h[i];
            oc[i] = g_c[i];
        }
    }
}

extern "C" void kernel_launch(void* const* d_in, const int* in_sizes, int n_in,
                              void* d_out, int out_size)
{
    prepack_kernel<<<NBLK, NTHR>>>(
        (const float*)d_in[4],  (const float*)d_in[5],
        (const float*)d_in[8],  (const float*)d_in[9],
        (const float*)d_in[14], (const float*)d_in[16],
        (const float*)d_in[18], (const float*)d_in[0]);
    cudaFuncSetAttribute(critic_kernel,
                         cudaFuncAttributeMaxDynamicSharedMemorySize, 65536);
    critic_kernel<<<NBLK, NTHR, 65536>>>(
        (const float*)d_in[0],  (const int*)d_in[1],
        (const float*)d_in[2],  (const float*)d_in[3],
        (const float*)d_in[6],  (const float*)d_in[7],
        (const float*)d_in[10], (const float*)d_in[11],
        (const float*)d_in[12], (const float*)d_in[13],
        (const float*)d_in[15], (const float*)d_in[17],
        (const float*)d_in[19],
        (const float*)d_in[20], (const float*)d_in[21],
        (float*)d_out, out_size);
}